// round 6
// baseline (speedup 1.0000x reference)
#include <cuda_runtime.h>
#include <cuda_bf16.h>
#include <cooperative_groups.h>
#include <cstdint>

namespace cg = cooperative_groups;

// Problem dims (fixed by the dataset): N=100000, E=1000000, in=out=64
#define MAXN 100000
#define MAXE 1000000
#define DIM 64

// ---------------- scratch (static device globals; no allocation) -----------
__device__ float g_h0[MAXN * DIM];   // h for branch 0 (login)
__device__ float g_h1[MAXN * DIM];   // h for branch 1 (exec)
__device__ float g_s0[MAXN], g_d0[MAXN], g_s1[MAXN], g_d1[MAXN];

__device__ int    g_cnt[MAXN];       // per-dst in-degree
__device__ int    g_rs[MAXN + 1];    // CSR row offsets
__device__ int    g_head[MAXN];      // running insert cursor
__device__ int    g_bsum[128];       // scan tile sums
__device__ float2 g_edge[MAXE];      // dst-sorted: {bits(src|type<<30), p}

__device__ __forceinline__ float leakyf(float v) {
    return v > 0.f ? v : 0.2f * v;
}

// Packed f32x2 FMA (Blackwell-only; 2x fp32 FMA throughput)
#define FMA_F32X2(d, a, b, c) \
    asm("fma.rn.f32x2 %0, %1, %2, %3;" \
        : "=l"(d) : "l"(a), "l"(b), "l"(c))
#define PACK2(out, lo, hi) \
    asm("mov.b64 %0, {%1, %2};" : "=l"(out) : "r"(lo), "r"(hi))
#define UNPACK2(lo, hi, in) \
    asm("mov.b64 {%0, %1}, %2;" : "=r"(lo), "=r"(hi) : "l"(in))

#define XS_STRIDE 10   // floats per k-row (8 nodes + 2 pad; even for LDS.64 align)

// ---------------- K1: h = x@W via fma.rn.f32x2; s/d scalars -----------------
__global__ __launch_bounds__(256) void k_gemm(
    const float* __restrict__ x,
    const float* __restrict__ W0, const float* __restrict__ W1,
    const float* __restrict__ as0, const float* __restrict__ ad0,
    const float* __restrict__ as1, const float* __restrict__ ad1,
    int N)
{
    __shared__ float Ws[2 * DIM * DIM];          // [mat][k][col], 32 KB
    __shared__ float xs[8][DIM * XS_STRIDE];     // k-major per warp, 20 KB

    int tid = threadIdx.x;
    for (int i = tid; i < DIM * DIM; i += 256) {
        Ws[i] = W0[i];
        Ws[DIM * DIM + i] = W1[i];
    }
    __syncthreads();

    int warp = tid >> 5, lane = tid & 31;
    int sel = lane >> 4;          // 0 -> branch0, 1 -> branch1
    int li  = lane & 15;          // 16 lanes cover 64 cols (4 each)
    const float* myW = Ws + sel * DIM * DIM;
    float4 asv = *reinterpret_cast<const float4*>((sel ? as1 : as0) + 4 * li);
    float4 adv = *reinterpret_cast<const float4*>((sel ? ad1 : ad0) + 4 * li);
    float* myH = sel ? g_h1 : g_h0;
    float* myS = sel ? g_s1 : g_s0;
    float* myD = sel ? g_d1 : g_d0;

    int nChunks = (N + 7) >> 3;
    for (int chunk = blockIdx.x * 8 + warp; chunk < nChunks; chunk += gridDim.x * 8) {
        int base = chunk * 8;
        int count = min(8, N - base);

        // stage x transposed: xs[k*XS_STRIDE + r] = x[base+r][k]
        {
            const float4* x4 = reinterpret_cast<const float4*>(x) + (size_t)base * 16;
            float* xw = xs[warp];
            for (int i = lane; i < 128; i += 32) {
                int r = i >> 4, k4 = i & 15;
                float4 v = (r < count) ? x4[i] : make_float4(0.f, 0.f, 0.f, 0.f);
                xw[(4 * k4 + 0) * XS_STRIDE + r] = v.x;
                xw[(4 * k4 + 1) * XS_STRIDE + r] = v.y;
                xw[(4 * k4 + 2) * XS_STRIDE + r] = v.z;
                xw[(4 * k4 + 3) * XS_STRIDE + r] = v.w;
            }
        }
        __syncwarp();

        unsigned long long accp[4][4];
#pragma unroll
        for (int p = 0; p < 4; p++)
#pragma unroll
            for (int c = 0; c < 4; c++) accp[p][c] = 0ull;

        const float* xw = xs[warp];
#pragma unroll 8
        for (int k = 0; k < DIM; k++) {
            float4 wv = *reinterpret_cast<const float4*>(myW + k * DIM + 4 * li);
            unsigned long long b[4];
            PACK2(b[0], __float_as_uint(wv.x), __float_as_uint(wv.x));
            PACK2(b[1], __float_as_uint(wv.y), __float_as_uint(wv.y));
            PACK2(b[2], __float_as_uint(wv.z), __float_as_uint(wv.z));
            PACK2(b[3], __float_as_uint(wv.w), __float_as_uint(wv.w));
            const float* xrow = xw + k * XS_STRIDE;
#pragma unroll
            for (int p = 0; p < 4; p++) {
                unsigned long long a =
                    *reinterpret_cast<const unsigned long long*>(xrow + 2 * p);
                FMA_F32X2(accp[p][0], a, b[0], accp[p][0]);
                FMA_F32X2(accp[p][1], a, b[1], accp[p][1]);
                FMA_F32X2(accp[p][2], a, b[2], accp[p][2]);
                FMA_F32X2(accp[p][3], a, b[3], accp[p][3]);
            }
        }

        float hval[8][4];
#pragma unroll
        for (int p = 0; p < 4; p++)
#pragma unroll
            for (int c = 0; c < 4; c++) {
                unsigned lo, hi;
                UNPACK2(lo, hi, accp[p][c]);
                hval[2 * p][c] = __uint_as_float(lo);
                hval[2 * p + 1][c] = __uint_as_float(hi);
            }

        for (int r = 0; r < count; r++) {
            int node = base + r;
            float4 hv = make_float4(hval[r][0], hval[r][1], hval[r][2], hval[r][3]);
            *reinterpret_cast<float4*>(myH + (size_t)node * DIM + 4 * li) = hv;

            float ps = hv.x * asv.x + hv.y * asv.y + hv.z * asv.z + hv.w * asv.w;
            float pd = hv.x * adv.x + hv.y * adv.y + hv.z * adv.z + hv.w * adv.w;
#pragma unroll
            for (int off = 8; off > 0; off >>= 1) {
                ps += __shfl_down_sync(0xffffffffu, ps, off, 16);
                pd += __shfl_down_sync(0xffffffffu, pd, off, 16);
            }
            if (li == 0) {
                myS[node] = ps;
                myD[node] = pd;
            }
        }
        __syncwarp();
    }
}

// ---------------- K2 (cooperative): zero + hist + scan + place --------------
// One kernel, grid.sync between phases. Eliminates 4 launch boundaries and
// re-reads dst from a hot L2.
__global__ __launch_bounds__(256) void k_csr(
    const int* __restrict__ src, const int* __restrict__ dst,
    const int* __restrict__ etype, int N, int E)
{
    cg::grid_group grid = cg::this_grid();
    int tid = threadIdx.x;
    int gtid = blockIdx.x * 256 + tid;
    int gsz = gridDim.x * 256;
    int lane = tid & 31, w = tid >> 5;

    __shared__ int s_w[8];
    __shared__ int s_off;

    // ---- phase 0: zero counts ----
    for (int i = gtid; i < N; i += gsz) g_cnt[i] = 0;
    grid.sync();

    // ---- phase 1: histogram of destinations ----
    int nE4 = E >> 2;
    for (int e4 = gtid; e4 < nE4; e4 += gsz) {
        int4 dv = reinterpret_cast<const int4*>(dst)[e4];
        atomicAdd(&g_cnt[dv.x], 1);
        atomicAdd(&g_cnt[dv.y], 1);
        atomicAdd(&g_cnt[dv.z], 1);
        atomicAdd(&g_cnt[dv.w], 1);
    }
    for (int e = nE4 * 4 + gtid; e < E; e += gsz) atomicAdd(&g_cnt[dst[e]], 1);
    grid.sync();

    // ---- phase 2: per-tile (1024 nodes) exclusive scan ----
    int nTiles = (N + 1023) >> 10;
    for (int tile = blockIdx.x; tile < nTiles; tile += gridDim.x) {
        int base = (tile << 10) + tid * 4;
        int v0 = 0, v1 = 0, v2 = 0, v3 = 0;
        if (base + 3 < N) {
            int4 c = *reinterpret_cast<const int4*>(g_cnt + base);
            v0 = c.x; v1 = c.y; v2 = c.z; v3 = c.w;
        } else {
            if (base     < N) v0 = g_cnt[base];
            if (base + 1 < N) v1 = g_cnt[base + 1];
            if (base + 2 < N) v2 = g_cnt[base + 2];
            if (base + 3 < N) v3 = g_cnt[base + 3];
        }
        int tsum = v0 + v1 + v2 + v3;
        int inc = tsum;
#pragma unroll
        for (int off = 1; off < 32; off <<= 1) {
            int y = __shfl_up_sync(0xffffffffu, inc, off);
            if (lane >= off) inc += y;
        }
        if (lane == 31) s_w[w] = inc;
        __syncthreads();
        if (tid < 8) {
            int s = s_w[tid];
#pragma unroll
            for (int off = 1; off < 8; off <<= 1) {
                int y = __shfl_up_sync(0xffu, s, off);
                if (tid >= off) s += y;
            }
            s_w[tid] = s;   // inclusive warp-sum scan
        }
        __syncthreads();
        int ex = inc - tsum + (w ? s_w[w - 1] : 0);   // thread-exclusive
        if (base + 3 < N) {
            int4 r = make_int4(ex, ex + v0, ex + v0 + v1, ex + v0 + v1 + v2);
            *reinterpret_cast<int4*>(g_rs + base) = r;
        } else {
            if (base     < N) g_rs[base]     = ex;
            if (base + 1 < N) g_rs[base + 1] = ex + v0;
            if (base + 2 < N) g_rs[base + 2] = ex + v0 + v1;
            if (base + 3 < N) g_rs[base + 3] = ex + v0 + v1 + v2;
        }
        if (tid == 255) g_bsum[tile] = ex + tsum;     // tile total
        __syncthreads();
    }
    grid.sync();

    // ---- phase 3: add tile offsets; init head; rs[N] ----
    if (gtid == 0) g_rs[N] = E;
    for (int tile = blockIdx.x; tile < nTiles; tile += gridDim.x) {
        int v = (tid < tile && tid < 128) ? g_bsum[tid] : 0;
#pragma unroll
        for (int off = 16; off > 0; off >>= 1)
            v += __shfl_down_sync(0xffffffffu, v, off);
        if (lane == 0) s_w[w] = v;
        __syncthreads();
        if (tid == 0) {
            int o = 0;
#pragma unroll
            for (int j = 0; j < 8; j++) o += s_w[j];
            s_off = o;
        }
        __syncthreads();
        int off = s_off;

        int base = (tile << 10) + tid * 4;
        if (base + 3 < N) {
            int4 r = *reinterpret_cast<const int4*>(g_rs + base);
            r.x += off; r.y += off; r.z += off; r.w += off;
            *reinterpret_cast<int4*>(g_rs + base) = r;
            *reinterpret_cast<int4*>(g_head + base) = r;
        } else {
            for (int j = 0; j < 4; j++) {
                if (base + j < N) {
                    int r = g_rs[base + j] + off;
                    g_rs[base + j] = r;
                    g_head[base + j] = r;
                }
            }
        }
        __syncthreads();
    }
    grid.sync();

    // ---- phase 4: place edges (p + CSR position) ----
    for (int e4 = gtid; e4 < nE4; e4 += gsz) {
        int4 sv = reinterpret_cast<const int4*>(src)[e4];
        int4 dv = reinterpret_cast<const int4*>(dst)[e4];
        int4 tv = reinterpret_cast<const int4*>(etype)[e4];
        int ss[4] = {sv.x, sv.y, sv.z, sv.w};
        int dd[4] = {dv.x, dv.y, dv.z, dv.w};
        int tt[4] = {tv.x, tv.y, tv.z, tv.w};
#pragma unroll
        for (int i = 0; i < 4; i++) {
            int s = ss[i], d = dd[i], t = tt[i];
            float svv = t ? g_s1[s] : g_s0[s];
            float dvv = t ? g_d1[d] : g_d0[d];
            float p = __expf(leakyf(svv + dvv));
            int pos = atomicAdd(&g_head[d], 1);
            g_edge[pos] = make_float2(__int_as_float(s | (t << 30)), p);
        }
    }
    for (int e = nE4 * 4 + gtid; e < E; e += gsz) {
        int s = src[e], d = dst[e], t = etype[e];
        float svv = t ? g_s1[s] : g_s0[s];
        float dvv = t ? g_d1[d] : g_d0[d];
        float p = __expf(leakyf(svv + dvv));
        int pos = atomicAdd(&g_head[d], 1);
        g_edge[pos] = make_float2(__int_as_float(s | (t << 30)), p);
    }
}

// ---------------- K3: gather — out[d] = Σ_t (acc_t + self_t·h_t)/den_t + b --
__global__ __launch_bounds__(256) void k_gather(
    const float* __restrict__ b0, const float* __restrict__ b1,
    float* __restrict__ out, int N)
{
    int gw = (blockIdx.x * blockDim.x + threadIdx.x) >> 5;
    int lane = threadIdx.x & 31;
    int sub = lane >> 4;
    int l = lane & 15;

    float4 bv;
    {
        float4 bb0 = reinterpret_cast<const float4*>(b0)[l];
        float4 bb1 = reinterpret_cast<const float4*>(b1)[l];
        bv = make_float4(bb0.x + bb1.x, bb0.y + bb1.y, bb0.z + bb1.z, bb0.w + bb1.w);
    }

    int node = gw * 2 + sub;
    bool live = node < N;
    int nc = live ? node : (N - 1);

    float selfp0 = __expf(leakyf(g_s0[nc] + g_d0[nc]));
    float selfp1 = __expf(leakyf(g_s1[nc] + g_d1[nc]));
    float den0 = selfp0, den1 = selfp1;

    const float4* h0r = reinterpret_cast<const float4*>(g_h0);
    const float4* h1r = reinterpret_cast<const float4*>(g_h1);

    float4 acc0 = make_float4(0.f, 0.f, 0.f, 0.f);
    float4 acc1 = make_float4(0.f, 0.f, 0.f, 0.f);

    int beg = g_rs[nc], end = g_rs[nc + 1];
    float2 ev = (beg < end) ? __ldg(&g_edge[beg]) : make_float2(0.f, 0.f);
    for (int ei = beg; ei < end; ei++) {
        float2 evn = (ei + 1 < end) ? __ldg(&g_edge[ei + 1]) : make_float2(0.f, 0.f);
        int pk = __float_as_int(ev.x);
        int s = pk & 0x3FFFFFFF;
        float ft = (float)(((unsigned)pk) >> 30);
        float w1 = ev.y * ft;
        float w0 = ev.y - w1;
        den0 += w0; den1 += w1;
        float4 hv = __ldg((ft != 0.f ? h1r : h0r) + (size_t)s * 16 + l);
        acc0.x = fmaf(w0, hv.x, acc0.x); acc1.x = fmaf(w1, hv.x, acc1.x);
        acc0.y = fmaf(w0, hv.y, acc0.y); acc1.y = fmaf(w1, hv.y, acc1.y);
        acc0.z = fmaf(w0, hv.z, acc0.z); acc1.z = fmaf(w1, hv.z, acc1.z);
        acc0.w = fmaf(w0, hv.w, acc0.w); acc1.w = fmaf(w1, hv.w, acc1.w);
        ev = evn;
    }

    float4 hv0 = __ldg(h0r + (size_t)nc * 16 + l);
    float4 hv1 = __ldg(h1r + (size_t)nc * 16 + l);
    float rd0 = 1.f / den0, rd1 = 1.f / den1;
    float4 o;
    o.x = (acc0.x + selfp0 * hv0.x) * rd0 + (acc1.x + selfp1 * hv1.x) * rd1 + bv.x;
    o.y = (acc0.y + selfp0 * hv0.y) * rd0 + (acc1.y + selfp1 * hv1.y) * rd1 + bv.y;
    o.z = (acc0.z + selfp0 * hv0.z) * rd0 + (acc1.z + selfp1 * hv1.z) * rd1 + bv.z;
    o.w = (acc0.w + selfp0 * hv0.w) * rd0 + (acc1.w + selfp1 * hv1.w) * rd1 + bv.w;

    if (live)
        reinterpret_cast<float4*>(out)[(size_t)node * 16 + l] = o;
}

// ---------------- launch -----------------------------------------------------
extern "C" void kernel_launch(void* const* d_in, const int* in_sizes, int n_in,
                              void* d_out, int out_size)
{
    const float* x   = (const float*)d_in[0];
    const int*   ei  = (const int*)  d_in[1];
    const int*   et  = (const int*)  d_in[2];
    const float* W0  = (const float*)d_in[3];
    const float* as0 = (const float*)d_in[4];
    const float* ad0 = (const float*)d_in[5];
    const float* b0  = (const float*)d_in[6];
    const float* W1  = (const float*)d_in[7];
    const float* as1 = (const float*)d_in[8];
    const float* ad1 = (const float*)d_in[9];
    const float* b1  = (const float*)d_in[10];
    float* out = (float*)d_out;

    int N = in_sizes[0] / DIM;
    int E = in_sizes[1] / 2;
    if (N > MAXN) N = MAXN;
    if (E > MAXE) E = MAXE;

    const int* srcp = ei;
    const int* dstp = ei + E;

    int nChunks = (N + 7) / 8;
    int gemmBlocks = (nChunks + 7) / 8;
    if (gemmBlocks > 1184) gemmBlocks = 1184;

    // cooperative grid size (computed once on the uncaptured correctness call)
    static int s_csrGrid = 0;
    if (s_csrGrid == 0) {
        int dev = 0, sms = 0, bpsm = 0;
        cudaGetDevice(&dev);
        cudaDeviceGetAttribute(&sms, cudaDevAttrMultiProcessorCount, dev);
        cudaOccupancyMaxActiveBlocksPerMultiprocessor(&bpsm, k_csr, 256, 0);
        if (bpsm < 1) bpsm = 1;
        s_csrGrid = sms * bpsm;
        if (s_csrGrid < 1) s_csrGrid = 1;
    }

    k_gemm<<<gemmBlocks, 256>>>(x, W0, W1, as0, ad0, as1, ad1, N);

    void* csrArgs[] = {(void*)&srcp, (void*)&dstp, (void*)&et,
                       (void*)&N, (void*)&E};
    cudaLaunchCooperativeKernel((void*)k_csr, dim3(s_csrGrid), dim3(256),
                                csrArgs, 0, 0);

    k_gather<<<(N + 15) / 16, 256>>>(b0, b1, out, N);
}

// round 7
// speedup vs baseline: 1.0147x; 1.0147x over previous
#include <cuda_runtime.h>
#include <cuda_bf16.h>
#include <cstdint>

// Problem dims (fixed by the dataset): N=100000, E=1000000, in=out=64
#define MAXN 100000
#define MAXE 1000000
#define DIM 64

// ---------------- scratch (static device globals; no allocation) -----------
__device__ float g_h0[MAXN * DIM];   // h for branch 0 (login)
__device__ float g_h1[MAXN * DIM];   // h for branch 1 (exec)
__device__ float g_s0[MAXN], g_d0[MAXN], g_s1[MAXN], g_d1[MAXN];

__device__ int    g_cnt[MAXN];       // per-dst in-degree
__device__ int    g_rs[MAXN + 1];    // CSR row offsets
__device__ int    g_head[MAXN];      // running insert cursor
__device__ int    g_bsum[128];       // scan block sums
__device__ float2 g_edge[MAXE];      // dst-sorted: {bits(src|type<<30), p}

__device__ __forceinline__ float leakyf(float v) {
    return v > 0.f ? v : 0.2f * v;
}

// Packed f32x2 FMA (Blackwell-only; 2x fp32 FMA throughput)
#define FMA_F32X2(d, a, b, c) \
    asm("fma.rn.f32x2 %0, %1, %2, %3;" \
        : "=l"(d) : "l"(a), "l"(b), "l"(c))
#define PACK2(out, lo, hi) \
    asm("mov.b64 %0, {%1, %2};" : "=l"(out) : "r"(lo), "r"(hi))
#define UNPACK2(lo, hi, in) \
    asm("mov.b64 {%0, %1}, %2;" : "=r"(lo), "=r"(hi) : "l"(in))

#define XS_STRIDE 10   // floats per k-row (8 nodes + 2 pad; even for LDS.64 align)

// ---------------- K1: h = x@W via fma.rn.f32x2; s/d scalars -----------------
// 4 blocks/SM target: <=64 regs, 52.5KB smem. Epilogue unpacks accp directly
// (no hval staging array) to keep register pressure down.
__global__ __launch_bounds__(256, 4) void k_gemm(
    const float* __restrict__ x,
    const float* __restrict__ W0, const float* __restrict__ W1,
    const float* __restrict__ as0, const float* __restrict__ ad0,
    const float* __restrict__ as1, const float* __restrict__ ad1,
    int N)
{
    __shared__ float Ws[2 * DIM * DIM];          // [mat][k][col], 32 KB
    __shared__ float xs[8][DIM * XS_STRIDE];     // k-major per warp, 20 KB

    int tid = threadIdx.x;
    for (int i = tid; i < DIM * DIM; i += 256) {
        Ws[i] = W0[i];
        Ws[DIM * DIM + i] = W1[i];
    }
    __syncthreads();

    int warp = tid >> 5, lane = tid & 31;
    int sel = lane >> 4;          // 0 -> branch0, 1 -> branch1
    int li  = lane & 15;          // 16 lanes cover 64 cols (4 each)
    const float* myW = Ws + sel * DIM * DIM;
    float4 asv = *reinterpret_cast<const float4*>((sel ? as1 : as0) + 4 * li);
    float4 adv = *reinterpret_cast<const float4*>((sel ? ad1 : ad0) + 4 * li);
    float* myH = sel ? g_h1 : g_h0;
    float* myS = sel ? g_s1 : g_s0;
    float* myD = sel ? g_d1 : g_d0;

    int nChunks = (N + 7) >> 3;
    for (int chunk = blockIdx.x * 8 + warp; chunk < nChunks; chunk += gridDim.x * 8) {
        int base = chunk * 8;
        int count = min(8, N - base);

        // stage x transposed: xs[k*XS_STRIDE + r] = x[base+r][k]
        {
            const float4* x4 = reinterpret_cast<const float4*>(x) + (size_t)base * 16;
            float* xw = xs[warp];
            for (int i = lane; i < 128; i += 32) {
                int r = i >> 4, k4 = i & 15;
                float4 v = (r < count) ? x4[i] : make_float4(0.f, 0.f, 0.f, 0.f);
                xw[(4 * k4 + 0) * XS_STRIDE + r] = v.x;
                xw[(4 * k4 + 1) * XS_STRIDE + r] = v.y;
                xw[(4 * k4 + 2) * XS_STRIDE + r] = v.z;
                xw[(4 * k4 + 3) * XS_STRIDE + r] = v.w;
            }
        }
        __syncwarp();

        unsigned long long accp[4][4];
#pragma unroll
        for (int p = 0; p < 4; p++)
#pragma unroll
            for (int c = 0; c < 4; c++) accp[p][c] = 0ull;

        const float* xw = xs[warp];
#pragma unroll 8
        for (int k = 0; k < DIM; k++) {
            float4 wv = *reinterpret_cast<const float4*>(myW + k * DIM + 4 * li);
            unsigned long long b[4];
            PACK2(b[0], __float_as_uint(wv.x), __float_as_uint(wv.x));
            PACK2(b[1], __float_as_uint(wv.y), __float_as_uint(wv.y));
            PACK2(b[2], __float_as_uint(wv.z), __float_as_uint(wv.z));
            PACK2(b[3], __float_as_uint(wv.w), __float_as_uint(wv.w));
            const float* xrow = xw + k * XS_STRIDE;
#pragma unroll
            for (int p = 0; p < 4; p++) {
                unsigned long long a =
                    *reinterpret_cast<const unsigned long long*>(xrow + 2 * p);
                FMA_F32X2(accp[p][0], a, b[0], accp[p][0]);
                FMA_F32X2(accp[p][1], a, b[1], accp[p][1]);
                FMA_F32X2(accp[p][2], a, b[2], accp[p][2]);
                FMA_F32X2(accp[p][3], a, b[3], accp[p][3]);
            }
        }

        // epilogue: unpack accumulator pairs in-place (no hval array)
#pragma unroll
        for (int p = 0; p < 4; p++) {
            int r0 = 2 * p, r1 = 2 * p + 1;
            unsigned lo0, hi0, lo1, hi1, lo2, hi2, lo3, hi3;
            UNPACK2(lo0, hi0, accp[p][0]);
            UNPACK2(lo1, hi1, accp[p][1]);
            UNPACK2(lo2, hi2, accp[p][2]);
            UNPACK2(lo3, hi3, accp[p][3]);

            float4 hvA = make_float4(__uint_as_float(lo0), __uint_as_float(lo1),
                                     __uint_as_float(lo2), __uint_as_float(lo3));
            float4 hvB = make_float4(__uint_as_float(hi0), __uint_as_float(hi1),
                                     __uint_as_float(hi2), __uint_as_float(hi3));

            // node r0
            {
                float ps = hvA.x * asv.x + hvA.y * asv.y + hvA.z * asv.z + hvA.w * asv.w;
                float pd = hvA.x * adv.x + hvA.y * adv.y + hvA.z * adv.z + hvA.w * adv.w;
#pragma unroll
                for (int off = 8; off > 0; off >>= 1) {
                    ps += __shfl_down_sync(0xffffffffu, ps, off, 16);
                    pd += __shfl_down_sync(0xffffffffu, pd, off, 16);
                }
                if (r0 < count) {
                    int node = base + r0;
                    *reinterpret_cast<float4*>(myH + (size_t)node * DIM + 4 * li) = hvA;
                    if (li == 0) { myS[node] = ps; myD[node] = pd; }
                }
            }
            // node r1
            {
                float ps = hvB.x * asv.x + hvB.y * asv.y + hvB.z * asv.z + hvB.w * asv.w;
                float pd = hvB.x * adv.x + hvB.y * adv.y + hvB.z * adv.z + hvB.w * adv.w;
#pragma unroll
                for (int off = 8; off > 0; off >>= 1) {
                    ps += __shfl_down_sync(0xffffffffu, ps, off, 16);
                    pd += __shfl_down_sync(0xffffffffu, pd, off, 16);
                }
                if (r1 < count) {
                    int node = base + r1;
                    *reinterpret_cast<float4*>(myH + (size_t)node * DIM + 4 * li) = hvB;
                    if (li == 0) { myS[node] = ps; myD[node] = pd; }
                }
            }
        }
        __syncwarp();
    }
}

// ---------------- K2: zero counts -------------------------------------------
__global__ __launch_bounds__(256) void k_zero(int N)
{
    int i = blockIdx.x * 256 + threadIdx.x;
    if (i < N) g_cnt[i] = 0;
}

// ---------------- K3: histogram of destinations -----------------------------
__global__ __launch_bounds__(256) void k_hist(const int* __restrict__ dst, int E)
{
    int e4 = blockIdx.x * 256 + threadIdx.x;
    int base = e4 * 4;
    if (base >= E) return;
    if (base + 3 < E) {
        int4 dv = reinterpret_cast<const int4*>(dst)[e4];
        atomicAdd(&g_cnt[dv.x], 1);
        atomicAdd(&g_cnt[dv.y], 1);
        atomicAdd(&g_cnt[dv.z], 1);
        atomicAdd(&g_cnt[dv.w], 1);
    } else {
        for (int e = base; e < E; e++) atomicAdd(&g_cnt[dst[e]], 1);
    }
}

// ---------------- K4a: scanA (block-local exclusive + block sums) -----------
__global__ __launch_bounds__(1024) void k_scanA(int N)
{
    __shared__ int warpSums[32];
    int i = blockIdx.x * 1024 + threadIdx.x;
    int lane = threadIdx.x & 31, w = threadIdx.x >> 5;
    int v = (i < N) ? g_cnt[i] : 0;
    int xv = v;
#pragma unroll
    for (int off = 1; off < 32; off <<= 1) {
        int y = __shfl_up_sync(0xffffffffu, xv, off);
        if (lane >= off) xv += y;
    }
    if (lane == 31) warpSums[w] = xv;
    __syncthreads();
    if (w == 0) {
        int s = warpSums[lane];
#pragma unroll
        for (int off = 1; off < 32; off <<= 1) {
            int y = __shfl_up_sync(0xffffffffu, s, off);
            if (lane >= off) s += y;
        }
        warpSums[lane] = s;
    }
    __syncthreads();
    if (w > 0) xv += warpSums[w - 1];
    if (i < N) g_rs[i] = xv - v;
    if (threadIdx.x == 1023) g_bsum[blockIdx.x] = xv;
}

// ---------------- K4b: scanC (inlines the block-sum scan) --------------------
__global__ __launch_bounds__(1024) void k_scanC(int N, int E)
{
    __shared__ int s_off;
    if (threadIdx.x == 0) s_off = 0;
    __syncthreads();
    if (threadIdx.x < 128) {
        int v = (threadIdx.x < blockIdx.x) ? g_bsum[threadIdx.x] : 0;
#pragma unroll
        for (int off = 16; off > 0; off >>= 1)
            v += __shfl_down_sync(0xffffffffu, v, off);
        if ((threadIdx.x & 31) == 0 && v) atomicAdd(&s_off, v);
    }
    __syncthreads();
    int boff = s_off;

    int i = blockIdx.x * 1024 + threadIdx.x;
    if (i < N) {
        int rs = g_rs[i] + boff;
        g_rs[i] = rs;
        g_head[i] = rs;
        if (i == N - 1) g_rs[N] = E;
    }
}

// ---------------- K5: edge pass — p + CSR placement --------------------------
__global__ __launch_bounds__(256) void k_place(
    const int* __restrict__ src, const int* __restrict__ dst,
    const int* __restrict__ etype, int E)
{
    int e4 = blockIdx.x * 256 + threadIdx.x;
    int base = e4 * 4;
    if (base >= E) return;

    int nE = min(4, E - base);
    int ss[4], dd[4], tt[4];
    if (nE == 4) {
        int4 sv = reinterpret_cast<const int4*>(src)[e4];
        int4 dv = reinterpret_cast<const int4*>(dst)[e4];
        int4 tv = reinterpret_cast<const int4*>(etype)[e4];
        ss[0] = sv.x; ss[1] = sv.y; ss[2] = sv.z; ss[3] = sv.w;
        dd[0] = dv.x; dd[1] = dv.y; dd[2] = dv.z; dd[3] = dv.w;
        tt[0] = tv.x; tt[1] = tv.y; tt[2] = tv.z; tt[3] = tv.w;
    } else {
        for (int i = 0; i < nE; i++) {
            ss[i] = src[base + i]; dd[i] = dst[base + i]; tt[i] = etype[base + i];
        }
    }
#pragma unroll 4
    for (int i = 0; i < 4; i++) {
        if (i >= nE) break;
        int s = ss[i], d = dd[i], t = tt[i];
        float sv = t ? g_s1[s] : g_s0[s];
        float dv = t ? g_d1[d] : g_d0[d];
        float p = __expf(leakyf(sv + dv));
        int pos = atomicAdd(&g_head[d], 1);
        g_edge[pos] = make_float2(__int_as_float(s | (t << 30)), p);
    }
}

// ---------------- K6: gather — out[d] = Σ_t (acc_t + self_t·h_t)/den_t + b --
__global__ __launch_bounds__(256) void k_gather(
    const float* __restrict__ b0, const float* __restrict__ b1,
    float* __restrict__ out, int N)
{
    int gw = (blockIdx.x * blockDim.x + threadIdx.x) >> 5;
    int lane = threadIdx.x & 31;
    int sub = lane >> 4;
    int l = lane & 15;

    float4 bv;
    {
        float4 bb0 = reinterpret_cast<const float4*>(b0)[l];
        float4 bb1 = reinterpret_cast<const float4*>(b1)[l];
        bv = make_float4(bb0.x + bb1.x, bb0.y + bb1.y, bb0.z + bb1.z, bb0.w + bb1.w);
    }

    int node = gw * 2 + sub;
    bool live = node < N;
    int nc = live ? node : (N - 1);

    float selfp0 = __expf(leakyf(g_s0[nc] + g_d0[nc]));
    float selfp1 = __expf(leakyf(g_s1[nc] + g_d1[nc]));
    float den0 = selfp0, den1 = selfp1;

    const float4* h0r = reinterpret_cast<const float4*>(g_h0);
    const float4* h1r = reinterpret_cast<const float4*>(g_h1);

    float4 acc0 = make_float4(0.f, 0.f, 0.f, 0.f);
    float4 acc1 = make_float4(0.f, 0.f, 0.f, 0.f);

    int beg = g_rs[nc], end = g_rs[nc + 1];
    float2 ev = (beg < end) ? __ldg(&g_edge[beg]) : make_float2(0.f, 0.f);
    for (int ei = beg; ei < end; ei++) {
        float2 evn = (ei + 1 < end) ? __ldg(&g_edge[ei + 1]) : make_float2(0.f, 0.f);
        int pk = __float_as_int(ev.x);
        int s = pk & 0x3FFFFFFF;
        float ft = (float)(((unsigned)pk) >> 30);
        float w1 = ev.y * ft;
        float w0 = ev.y - w1;
        den0 += w0; den1 += w1;
        float4 hv = __ldg((ft != 0.f ? h1r : h0r) + (size_t)s * 16 + l);
        acc0.x = fmaf(w0, hv.x, acc0.x); acc1.x = fmaf(w1, hv.x, acc1.x);
        acc0.y = fmaf(w0, hv.y, acc0.y); acc1.y = fmaf(w1, hv.y, acc1.y);
        acc0.z = fmaf(w0, hv.z, acc0.z); acc1.z = fmaf(w1, hv.z, acc1.z);
        acc0.w = fmaf(w0, hv.w, acc0.w); acc1.w = fmaf(w1, hv.w, acc1.w);
        ev = evn;
    }

    float4 hv0 = __ldg(h0r + (size_t)nc * 16 + l);
    float4 hv1 = __ldg(h1r + (size_t)nc * 16 + l);
    float rd0 = 1.f / den0, rd1 = 1.f / den1;
    float4 o;
    o.x = (acc0.x + selfp0 * hv0.x) * rd0 + (acc1.x + selfp1 * hv1.x) * rd1 + bv.x;
    o.y = (acc0.y + selfp0 * hv0.y) * rd0 + (acc1.y + selfp1 * hv1.y) * rd1 + bv.y;
    o.z = (acc0.z + selfp0 * hv0.z) * rd0 + (acc1.z + selfp1 * hv1.z) * rd1 + bv.z;
    o.w = (acc0.w + selfp0 * hv0.w) * rd0 + (acc1.w + selfp1 * hv1.w) * rd1 + bv.w;

    if (live)
        reinterpret_cast<float4*>(out)[(size_t)node * 16 + l] = o;
}

// ---------------- launch -----------------------------------------------------
extern "C" void kernel_launch(void* const* d_in, const int* in_sizes, int n_in,
                              void* d_out, int out_size)
{
    const float* x   = (const float*)d_in[0];
    const int*   ei  = (const int*)  d_in[1];
    const int*   et  = (const int*)  d_in[2];
    const float* W0  = (const float*)d_in[3];
    const float* as0 = (const float*)d_in[4];
    const float* ad0 = (const float*)d_in[5];
    const float* b0  = (const float*)d_in[6];
    const float* W1  = (const float*)d_in[7];
    const float* as1 = (const float*)d_in[8];
    const float* ad1 = (const float*)d_in[9];
    const float* b1  = (const float*)d_in[10];
    float* out = (float*)d_out;

    int N = in_sizes[0] / DIM;
    int E = in_sizes[1] / 2;
    if (N > MAXN) N = MAXN;
    if (E > MAXE) E = MAXE;

    const int* srcp = ei;
    const int* dstp = ei + E;

    int nChunks = (N + 7) / 8;
    int gemmBlocks = (nChunks + 7) / 8;
    if (gemmBlocks > 1184) gemmBlocks = 1184;

    int nScanBlocks = (N + 1023) / 1024;

    k_gemm <<<gemmBlocks, 256>>>(x, W0, W1, as0, ad0, as1, ad1, N);
    k_zero <<<(N + 255) / 256, 256>>>(N);
    k_hist <<<(E / 4 + 255) / 256 + 1, 256>>>(dstp, E);
    k_scanA<<<nScanBlocks, 1024>>>(N);
    k_scanC<<<nScanBlocks, 1024>>>(N, E);
    k_place<<<(E / 4 + 255) / 256 + 1, 256>>>(srcp, dstp, et, E);
    k_gather<<<(N + 15) / 16, 256>>>(b0, b1, out, N);
}

// round 8
// speedup vs baseline: 1.1656x; 1.1488x over previous
#include <cuda_runtime.h>
#include <cuda_bf16.h>
#include <cstdint>

// Problem dims (fixed by the dataset): N=100000, E=1000000, in=out=64
#define MAXN 100000
#define MAXE 1000000
#define DIM 64

// ---------------- scratch (static device globals; no allocation) -----------
__device__ float g_h0[MAXN * DIM];   // h for branch 0 (login)
__device__ float g_h1[MAXN * DIM];   // h for branch 1 (exec)
__device__ float g_s0[MAXN], g_d0[MAXN], g_s1[MAXN], g_d1[MAXN];

__device__ int    g_cnt[MAXN];       // per-dst in-degree
__device__ int    g_rs[MAXN + 1];    // CSR row offsets
__device__ int    g_head[MAXN];      // running insert cursor
__device__ int    g_bsum[128];       // scan block sums
__device__ float2 g_edge[MAXE];      // dst-sorted: {bits(src|type<<30), p}

__device__ __forceinline__ float leakyf(float v) {
    return v > 0.f ? v : 0.2f * v;
}

// Packed f32x2 FMA (Blackwell-only; 2x fp32 FMA throughput)
#define FMA_F32X2(d, a, b, c) \
    asm("fma.rn.f32x2 %0, %1, %2, %3;" \
        : "=l"(d) : "l"(a), "l"(b), "l"(c))
#define PACK2(out, lo, hi) \
    asm("mov.b64 %0, {%1, %2};" : "=l"(out) : "r"(lo), "r"(hi))
#define UNPACK2(lo, hi, in) \
    asm("mov.b64 {%0, %1}, %2;" : "=r"(lo), "=r"(hi) : "l"(in))

#define XS_STRIDE 10   // floats per k-row (8 nodes + 2 pad; even for LDS.64 align)

// ---------------- K1: h = x@W via fma.rn.f32x2; s/d scalars; cnt=0 ----------
// Natural register allocation (74 regs, 3 blocks/SM). Grid sized to exactly
// one resident wave (148 SMs x 3 blocks) so Ws is loaded once per block slot.
__global__ __launch_bounds__(256) void k_gemm(
    const float* __restrict__ x,
    const float* __restrict__ W0, const float* __restrict__ W1,
    const float* __restrict__ as0, const float* __restrict__ ad0,
    const float* __restrict__ as1, const float* __restrict__ ad1,
    int N)
{
    __shared__ float Ws[2 * DIM * DIM];          // [mat][k][col], 32 KB
    __shared__ float xs[8][DIM * XS_STRIDE];     // k-major per warp, 20 KB

    int tid = threadIdx.x;
    for (int i = tid; i < DIM * DIM; i += 256) {
        Ws[i] = W0[i];
        Ws[DIM * DIM + i] = W1[i];
    }
    __syncthreads();

    int warp = tid >> 5, lane = tid & 31;
    int sel = lane >> 4;          // 0 -> branch0, 1 -> branch1
    int li  = lane & 15;          // 16 lanes cover 64 cols (4 each)
    const float* myW = Ws + sel * DIM * DIM;
    float4 asv = *reinterpret_cast<const float4*>((sel ? as1 : as0) + 4 * li);
    float4 adv = *reinterpret_cast<const float4*>((sel ? ad1 : ad0) + 4 * li);
    float* myH = sel ? g_h1 : g_h0;
    float* myS = sel ? g_s1 : g_s0;
    float* myD = sel ? g_d1 : g_d0;

    int nChunks = (N + 7) >> 3;
    for (int chunk = blockIdx.x * 8 + warp; chunk < nChunks; chunk += gridDim.x * 8) {
        int base = chunk * 8;
        int count = min(8, N - base);

        // stage x transposed: xs[k*XS_STRIDE + r] = x[base+r][k]
        {
            const float4* x4 = reinterpret_cast<const float4*>(x) + (size_t)base * 16;
            float* xw = xs[warp];
            for (int i = lane; i < 128; i += 32) {
                int r = i >> 4, k4 = i & 15;
                float4 v = (r < count) ? x4[i] : make_float4(0.f, 0.f, 0.f, 0.f);
                xw[(4 * k4 + 0) * XS_STRIDE + r] = v.x;
                xw[(4 * k4 + 1) * XS_STRIDE + r] = v.y;
                xw[(4 * k4 + 2) * XS_STRIDE + r] = v.z;
                xw[(4 * k4 + 3) * XS_STRIDE + r] = v.w;
            }
        }
        __syncwarp();

        unsigned long long accp[4][4];
#pragma unroll
        for (int p = 0; p < 4; p++)
#pragma unroll
            for (int c = 0; c < 4; c++) accp[p][c] = 0ull;

        const float* xw = xs[warp];
#pragma unroll 8
        for (int k = 0; k < DIM; k++) {
            float4 wv = *reinterpret_cast<const float4*>(myW + k * DIM + 4 * li);
            unsigned long long b[4];
            PACK2(b[0], __float_as_uint(wv.x), __float_as_uint(wv.x));
            PACK2(b[1], __float_as_uint(wv.y), __float_as_uint(wv.y));
            PACK2(b[2], __float_as_uint(wv.z), __float_as_uint(wv.z));
            PACK2(b[3], __float_as_uint(wv.w), __float_as_uint(wv.w));
            const float* xrow = xw + k * XS_STRIDE;
#pragma unroll
            for (int p = 0; p < 4; p++) {
                unsigned long long a =
                    *reinterpret_cast<const unsigned long long*>(xrow + 2 * p);
                FMA_F32X2(accp[p][0], a, b[0], accp[p][0]);
                FMA_F32X2(accp[p][1], a, b[1], accp[p][1]);
                FMA_F32X2(accp[p][2], a, b[2], accp[p][2]);
                FMA_F32X2(accp[p][3], a, b[3], accp[p][3]);
            }
        }

        float hval[8][4];
#pragma unroll
        for (int p = 0; p < 4; p++)
#pragma unroll
            for (int c = 0; c < 4; c++) {
                unsigned lo, hi;
                UNPACK2(lo, hi, accp[p][c]);
                hval[2 * p][c] = __uint_as_float(lo);
                hval[2 * p + 1][c] = __uint_as_float(hi);
            }

        for (int r = 0; r < count; r++) {
            int node = base + r;
            float4 hv = make_float4(hval[r][0], hval[r][1], hval[r][2], hval[r][3]);
            *reinterpret_cast<float4*>(myH + (size_t)node * DIM + 4 * li) = hv;

            float ps = hv.x * asv.x + hv.y * asv.y + hv.z * asv.z + hv.w * asv.w;
            float pd = hv.x * adv.x + hv.y * adv.y + hv.z * adv.z + hv.w * adv.w;
#pragma unroll
            for (int off = 8; off > 0; off >>= 1) {
                ps += __shfl_down_sync(0xffffffffu, ps, off, 16);
                pd += __shfl_down_sync(0xffffffffu, pd, off, 16);
            }
            if (li == 0) {
                myS[node] = ps;
                myD[node] = pd;
                if (sel == 0) g_cnt[node] = 0;   // fold count-zeroing in here
            }
        }
        __syncwarp();
    }
}

// ---------------- K2: histogram of destinations -----------------------------
__global__ __launch_bounds__(256) void k_hist(const int* __restrict__ dst, int E)
{
    int e4 = blockIdx.x * 256 + threadIdx.x;
    int base = e4 * 4;
    if (base >= E) return;
    if (base + 3 < E) {
        int4 dv = reinterpret_cast<const int4*>(dst)[e4];
        atomicAdd(&g_cnt[dv.x], 1);
        atomicAdd(&g_cnt[dv.y], 1);
        atomicAdd(&g_cnt[dv.z], 1);
        atomicAdd(&g_cnt[dv.w], 1);
    } else {
        for (int e = base; e < E; e++) atomicAdd(&g_cnt[dst[e]], 1);
    }
}

// ---------------- K3a: scanA (block-local exclusive + block sums) -----------
__global__ __launch_bounds__(1024) void k_scanA(int N)
{
    __shared__ int warpSums[32];
    int i = blockIdx.x * 1024 + threadIdx.x;
    int lane = threadIdx.x & 31, w = threadIdx.x >> 5;
    int v = (i < N) ? g_cnt[i] : 0;
    int xv = v;
#pragma unroll
    for (int off = 1; off < 32; off <<= 1) {
        int y = __shfl_up_sync(0xffffffffu, xv, off);
        if (lane >= off) xv += y;
    }
    if (lane == 31) warpSums[w] = xv;
    __syncthreads();
    if (w == 0) {
        int s = warpSums[lane];
#pragma unroll
        for (int off = 1; off < 32; off <<= 1) {
            int y = __shfl_up_sync(0xffffffffu, s, off);
            if (lane >= off) s += y;
        }
        warpSums[lane] = s;
    }
    __syncthreads();
    if (w > 0) xv += warpSums[w - 1];
    if (i < N) g_rs[i] = xv - v;
    if (threadIdx.x == 1023) g_bsum[blockIdx.x] = xv;
}

// ---------------- K3b: scanC (inlines the block-sum scan) --------------------
__global__ __launch_bounds__(1024) void k_scanC(int N, int E)
{
    __shared__ int s_off;
    if (threadIdx.x == 0) s_off = 0;
    __syncthreads();
    if (threadIdx.x < 128) {
        int v = (threadIdx.x < blockIdx.x) ? g_bsum[threadIdx.x] : 0;
#pragma unroll
        for (int off = 16; off > 0; off >>= 1)
            v += __shfl_down_sync(0xffffffffu, v, off);
        if ((threadIdx.x & 31) == 0 && v) atomicAdd(&s_off, v);
    }
    __syncthreads();
    int boff = s_off;

    int i = blockIdx.x * 1024 + threadIdx.x;
    if (i < N) {
        int rs = g_rs[i] + boff;
        g_rs[i] = rs;
        g_head[i] = rs;
        if (i == N - 1) g_rs[N] = E;
    }
}

// ---------------- K4: edge pass — p + CSR placement --------------------------
__global__ __launch_bounds__(256) void k_place(
    const int* __restrict__ src, const int* __restrict__ dst,
    const int* __restrict__ etype, int E)
{
    int e4 = blockIdx.x * 256 + threadIdx.x;
    int base = e4 * 4;
    if (base >= E) return;

    int nE = min(4, E - base);
    int ss[4], dd[4], tt[4];
    if (nE == 4) {
        int4 sv = reinterpret_cast<const int4*>(src)[e4];
        int4 dv = reinterpret_cast<const int4*>(dst)[e4];
        int4 tv = reinterpret_cast<const int4*>(etype)[e4];
        ss[0] = sv.x; ss[1] = sv.y; ss[2] = sv.z; ss[3] = sv.w;
        dd[0] = dv.x; dd[1] = dv.y; dd[2] = dv.z; dd[3] = dv.w;
        tt[0] = tv.x; tt[1] = tv.y; tt[2] = tv.z; tt[3] = tv.w;
    } else {
        for (int i = 0; i < nE; i++) {
            ss[i] = src[base + i]; dd[i] = dst[base + i]; tt[i] = etype[base + i];
        }
    }
#pragma unroll 4
    for (int i = 0; i < 4; i++) {
        if (i >= nE) break;
        int s = ss[i], d = dd[i], t = tt[i];
        float sv = t ? g_s1[s] : g_s0[s];
        float dv = t ? g_d1[d] : g_d0[d];
        float p = __expf(leakyf(sv + dv));
        int pos = atomicAdd(&g_head[d], 1);
        g_edge[pos] = make_float2(__int_as_float(s | (t << 30)), p);
    }
}

// ---------------- K5: gather — out[d] = Σ_t (acc_t + self_t·h_t)/den_t + b --
__global__ __launch_bounds__(256) void k_gather(
    const float* __restrict__ b0, const float* __restrict__ b1,
    float* __restrict__ out, int N)
{
    int gw = (blockIdx.x * blockDim.x + threadIdx.x) >> 5;
    int lane = threadIdx.x & 31;
    int sub = lane >> 4;
    int l = lane & 15;

    float4 bv;
    {
        float4 bb0 = reinterpret_cast<const float4*>(b0)[l];
        float4 bb1 = reinterpret_cast<const float4*>(b1)[l];
        bv = make_float4(bb0.x + bb1.x, bb0.y + bb1.y, bb0.z + bb1.z, bb0.w + bb1.w);
    }

    int node = gw * 2 + sub;
    bool live = node < N;
    int nc = live ? node : (N - 1);

    float selfp0 = __expf(leakyf(g_s0[nc] + g_d0[nc]));
    float selfp1 = __expf(leakyf(g_s1[nc] + g_d1[nc]));
    float den0 = selfp0, den1 = selfp1;

    const float4* h0r = reinterpret_cast<const float4*>(g_h0);
    const float4* h1r = reinterpret_cast<const float4*>(g_h1);

    float4 acc0 = make_float4(0.f, 0.f, 0.f, 0.f);
    float4 acc1 = make_float4(0.f, 0.f, 0.f, 0.f);

    int beg = g_rs[nc], end = g_rs[nc + 1];
    for (int ei = beg; ei < end; ei++) {
        float2 ev = g_edge[ei];                 // uniform address -> broadcast
        int pk = __float_as_int(ev.x);
        int s = pk & 0x3FFFFFFF;
        float ft = (float)(((unsigned)pk) >> 30);
        float w1 = ev.y * ft;
        float w0 = ev.y - w1;
        den0 += w0; den1 += w1;
        const float4* hp = (ft != 0.f ? h1r : h0r) + (size_t)s * 16;
        float4 hv = hp[l];
        acc0.x = fmaf(w0, hv.x, acc0.x); acc1.x = fmaf(w1, hv.x, acc1.x);
        acc0.y = fmaf(w0, hv.y, acc0.y); acc1.y = fmaf(w1, hv.y, acc1.y);
        acc0.z = fmaf(w0, hv.z, acc0.z); acc1.z = fmaf(w1, hv.z, acc1.z);
        acc0.w = fmaf(w0, hv.w, acc0.w); acc1.w = fmaf(w1, hv.w, acc1.w);
    }

    float4 hv0 = h0r[(size_t)nc * 16 + l];
    float4 hv1 = h1r[(size_t)nc * 16 + l];
    float rd0 = 1.f / den0, rd1 = 1.f / den1;
    float4 o;
    o.x = (acc0.x + selfp0 * hv0.x) * rd0 + (acc1.x + selfp1 * hv1.x) * rd1 + bv.x;
    o.y = (acc0.y + selfp0 * hv0.y) * rd0 + (acc1.y + selfp1 * hv1.y) * rd1 + bv.y;
    o.z = (acc0.z + selfp0 * hv0.z) * rd0 + (acc1.z + selfp1 * hv1.z) * rd1 + bv.z;
    o.w = (acc0.w + selfp0 * hv0.w) * rd0 + (acc1.w + selfp1 * hv1.w) * rd1 + bv.w;

    if (live)
        reinterpret_cast<float4*>(out)[(size_t)node * 16 + l] = o;
}

// ---------------- launch -----------------------------------------------------
extern "C" void kernel_launch(void* const* d_in, const int* in_sizes, int n_in,
                              void* d_out, int out_size)
{
    const float* x   = (const float*)d_in[0];
    const int*   ei  = (const int*)  d_in[1];
    const int*   et  = (const int*)  d_in[2];
    const float* W0  = (const float*)d_in[3];
    const float* as0 = (const float*)d_in[4];
    const float* ad0 = (const float*)d_in[5];
    const float* b0  = (const float*)d_in[6];
    const float* W1  = (const float*)d_in[7];
    const float* as1 = (const float*)d_in[8];
    const float* ad1 = (const float*)d_in[9];
    const float* b1  = (const float*)d_in[10];
    float* out = (float*)d_out;

    int N = in_sizes[0] / DIM;
    int E = in_sizes[1] / 2;
    if (N > MAXN) N = MAXN;
    if (E > MAXE) E = MAXE;

    const int* srcp = ei;
    const int* dstp = ei + E;

    // One resident wave: 148 SMs x 3 blocks/SM (74 regs) = 444 blocks.
    int nChunks = (N + 7) / 8;
    int gemmBlocks = (nChunks + 7) / 8;
    if (gemmBlocks > 444) gemmBlocks = 444;

    int nScanBlocks = (N + 1023) / 1024;

    k_gemm <<<gemmBlocks, 256>>>(x, W0, W1, as0, ad0, as1, ad1, N);
    k_hist <<<(E / 4 + 255) / 256 + 1, 256>>>(dstp, E);
    k_scanA<<<nScanBlocks, 1024>>>(N);
    k_scanC<<<nScanBlocks, 1024>>>(N, E);
    k_place<<<(E / 4 + 255) / 256 + 1, 256>>>(srcp, dstp, et, E);
    k_gather<<<(N + 15) / 16, 256>>>(b0, b1, out, N);
}